// round 1
// baseline (speedup 1.0000x reference)
#include <cuda_runtime.h>
#include <cuda_bf16.h>

// EmbeddedGCN: out[b,i,o] = relu( sum_j adj[b,i,j] * (concat(s1,s2)[b,i,j,:] @ W)[o] + bias[o] )
// Rewritten via linearity:
//   y[b,i,f]   = sum_j adj[b,i,j] * concat(s1,s2)[b,i,j,f]      (masked, load-gated reduce)
//   out[b,i,o] = relu( sum_f y[f]*W[f,o] + bias[o]*rowsum(adj) )
//
// B=16, M=128, F_IN_EACH=64 (concat -> 128), F_OUT=128.

#define BM 128   // M (neighbors / nodes)
#define FE 64    // features per source tensor
#define FT 128   // concatenated in-features
#define FO 128   // out-features

__global__ __launch_bounds__(128, 8)
void gcn_fused(const float* __restrict__ s1,
               const float* __restrict__ s2,
               const float* __restrict__ adj,
               const float* __restrict__ W,
               const float* __restrict__ bias,
               float* __restrict__ out)
{
    __shared__ float adj_s[BM];
    __shared__ int   jidx_s[BM];
    __shared__ float aval_s[BM];
    __shared__ float part_s[4][FT];
    __shared__ float y_s[FT];
    __shared__ int   cnt_s;
    __shared__ float rowsum_s;

    const int bi   = blockIdx.x;      // b*M + i
    const int tid  = threadIdx.x;     // 0..127
    const int lane = tid & 31;
    const int w    = tid >> 5;

    if (tid == 0) { cnt_s = 0; rowsum_s = 0.0f; }
    __syncthreads();

    // Load adjacency row; compact nonzero neighbor indices (load gating).
    {
        const float a = adj[bi * BM + tid];
        adj_s[tid] = a;
        if (a != 0.0f) {
            const int p = atomicAdd(&cnt_s, 1);
            jidx_s[p] = tid;
            aval_s[p] = a;
            atomicAdd(&rowsum_s, a);
        }
    }
    __syncthreads();
    const int cnt = cnt_s;

    // Each warp owns a strided slice of the compacted neighbor list.
    // Lane -> one float4 (4 features) of the 128-wide concat row:
    //   lanes 0..15  -> s1 row, float4 idx = lane       (features 0..63)
    //   lanes 16..31 -> s2 row, float4 idx = lane - 16  (features 64..127)
    const float4* base;
    {
        const size_t row0 = (size_t)bi * (size_t)(BM * FE);
        if (lane < 16) base = (const float4*)(s1 + row0) + lane;
        else           base = (const float4*)(s2 + row0) + (lane - 16);
    }

    float4 acc = make_float4(0.f, 0.f, 0.f, 0.f);
    // Manual 2x pipeline for a bit of MLP; warp-uniform j per iteration.
    int k = w;
    for (; k + 4 < cnt; k += 8) {
        const int   j0 = jidx_s[k];
        const int   j1 = jidx_s[k + 4];
        const float a0 = aval_s[k];
        const float a1 = aval_s[k + 4];
        const float4 v0 = __ldg(base + (size_t)j0 * 16);
        const float4 v1 = __ldg(base + (size_t)j1 * 16);
        acc.x = fmaf(a0, v0.x, acc.x);
        acc.y = fmaf(a0, v0.y, acc.y);
        acc.z = fmaf(a0, v0.z, acc.z);
        acc.w = fmaf(a0, v0.w, acc.w);
        acc.x = fmaf(a1, v1.x, acc.x);
        acc.y = fmaf(a1, v1.y, acc.y);
        acc.z = fmaf(a1, v1.z, acc.z);
        acc.w = fmaf(a1, v1.w, acc.w);
    }
    for (; k < cnt; k += 4) {
        const int   j = jidx_s[k];
        const float a = aval_s[k];
        const float4 v = __ldg(base + (size_t)j * 16);
        acc.x = fmaf(a, v.x, acc.x);
        acc.y = fmaf(a, v.y, acc.y);
        acc.z = fmaf(a, v.z, acc.z);
        acc.w = fmaf(a, v.w, acc.w);
    }

    part_s[w][lane * 4 + 0] = acc.x;
    part_s[w][lane * 4 + 1] = acc.y;
    part_s[w][lane * 4 + 2] = acc.z;
    part_s[w][lane * 4 + 3] = acc.w;
    __syncthreads();

    y_s[tid] = part_s[0][tid] + part_s[1][tid] + part_s[2][tid] + part_s[3][tid];
    __syncthreads();

    // Phase 2: 2048x128x128 GEMM fragment per block; W stays hot in L2 (64 KB).
    const int o = tid;
    float accO = bias[o] * rowsum_s;
    #pragma unroll 16
    for (int f = 0; f < FT; f++) {
        accO = fmaf(y_s[f], __ldg(W + f * FO + o), accO);
    }
    out[bi * FO + o] = fmaxf(accO, 0.0f);
}

extern "C" void kernel_launch(void* const* d_in, const int* in_sizes, int n_in,
                              void* d_out, int out_size)
{
    const float* s1   = (const float*)d_in[0];  // (16,128,128,64)
    const float* s2   = (const float*)d_in[1];  // (16,128,128,64)
    const float* adj  = (const float*)d_in[2];  // (16,128,128)
    const float* W    = (const float*)d_in[3];  // (128,128)
    const float* bias = (const float*)d_in[4];  // (128,)
    float* out = (float*)d_out;                 // (16,128,128)

    gcn_fused<<<16 * 128, 128>>>(s1, s2, adj, W, bias, out);
}

// round 3
// speedup vs baseline: 1.4819x; 1.4819x over previous
#include <cuda_runtime.h>
#include <cuda_bf16.h>

// EmbeddedGCN: out[b,i,o] = relu( sum_j adj[b,i,j] * (concat(s1,s2)[b,i,j,:] @ W)[o] + bias[o] )
// Linearity rewrite:
//   y[b,i,f]   = sum_j adj[b,i,j] * concat(s1,s2)[b,i,j,f]     (gated gather-reduce)
//   out[b,i,o] = relu( sum_f y[f]*W[f,o] + bias[o]*rowsum(adj) )
//
// B=16, M=128, FE=64 (concat -> 128), FO=128.
// Block = 256 threads (8 warps) handles R=8 rows (flat bi). Grid = 2048/8 = 256.
//  Phase 1: warp w gathers row bi0+w. Ballot compaction, MLP-8 batched loads.
//  Phase 2: W amortized over 8 rows; each thread owns (col o, 4 rows).

#define BM 128
#define FE 64
#define FT 128
#define FO 128
#define RPB 8     // rows per block

__global__ __launch_bounds__(256, 2)
void gcn_fused2(const float* __restrict__ s1,
                const float* __restrict__ s2,
                const float* __restrict__ adj,
                const float* __restrict__ W,
                const float* __restrict__ bias,
                float* __restrict__ out)
{
    __shared__ int   jidx_s[RPB][BM];
    __shared__ float aval_s[RPB][BM];
    __shared__ float y_s[RPB][FT];
    __shared__ float rowsum_s[RPB];

    const int tid  = threadIdx.x;
    const int lane = tid & 31;
    const int w    = tid >> 5;               // warp id = local row id
    const int bi0  = blockIdx.x * RPB;
    const int row  = bi0 + w;                // flat b*M + i

    // ---- Phase 1a: load adjacency row, warp-prefix compaction ----
    const float4 av = *(const float4*)(adj + (size_t)row * BM + lane * 4);
    int   cnt  = 0;
    float rsum = 0.0f;
    {
        const unsigned lt = (1u << lane) - 1u;
        #pragma unroll
        for (int r = 0; r < 4; r++) {
            const float a = (r == 0) ? av.x : (r == 1) ? av.y : (r == 2) ? av.z : av.w;
            const unsigned m = __ballot_sync(0xFFFFFFFFu, a != 0.0f);
            if (a != 0.0f) {
                const int pos = cnt + __popc(m & lt);
                jidx_s[w][pos] = lane * 4 + r;
                aval_s[w][pos] = a;
            }
            cnt  += __popc(m);
            rsum += a;
        }
        #pragma unroll
        for (int off = 16; off > 0; off >>= 1)
            rsum += __shfl_xor_sync(0xFFFFFFFFu, rsum, off);
        if (lane == 0) rowsum_s[w] = rsum;
    }
    __syncwarp();

    // ---- Phase 1b: gated gather-reduce, MLP=8 ----
    // lane -> one float4 of the 128-wide concat row:
    //   lanes 0..15  -> s1, float4 idx = lane        (features 0..63)
    //   lanes 16..31 -> s2, float4 idx = lane - 16   (features 64..127)
    const float4* base4;
    {
        const size_t row0 = (size_t)row * (size_t)(BM * FE);
        base4 = (lane < 16) ? ((const float4*)(s1 + row0) + lane)
                            : ((const float4*)(s2 + row0) + (lane - 16));
    }

    float4 acc = make_float4(0.f, 0.f, 0.f, 0.f);
    int k = 0;
    for (; k + 8 <= cnt; k += 8) {
        int   j[8];
        float a[8];
        float4 v[8];
        #pragma unroll
        for (int t = 0; t < 8; t++) { j[t] = jidx_s[w][k + t]; a[t] = aval_s[w][k + t]; }
        #pragma unroll
        for (int t = 0; t < 8; t++) v[t] = __ldg(base4 + (size_t)j[t] * 16);
        #pragma unroll
        for (int t = 0; t < 8; t++) {
            acc.x = fmaf(a[t], v[t].x, acc.x);
            acc.y = fmaf(a[t], v[t].y, acc.y);
            acc.z = fmaf(a[t], v[t].z, acc.z);
            acc.w = fmaf(a[t], v[t].w, acc.w);
        }
    }
    for (; k < cnt; k++) {
        const int   j = jidx_s[w][k];
        const float a = aval_s[w][k];
        const float4 v = __ldg(base4 + (size_t)j * 16);
        acc.x = fmaf(a, v.x, acc.x);
        acc.y = fmaf(a, v.y, acc.y);
        acc.z = fmaf(a, v.z, acc.z);
        acc.w = fmaf(a, v.w, acc.w);
    }

    {
        const int fb = (lane < 16) ? (lane * 4) : (FE + (lane - 16) * 4);
        *(float4*)&y_s[w][fb] = acc;
    }
    __syncthreads();

    // ---- Phase 2: out[r, o] = relu( y[r,:] @ W[:,o] + bias[o]*rowsum[r] ), W amortized 8x ----
    const int o  = tid & (FO - 1);
    const int g  = tid >> 7;                 // 0 or 1
    const int r0 = g * 4;

    float accO[4];
    {
        const float bo = __ldg(bias + o);
        #pragma unroll
        for (int q = 0; q < 4; q++) accO[q] = bo * rowsum_s[r0 + q];
    }

    #pragma unroll 8
    for (int f = 0; f < FT; f += 4) {
        const float w0 = __ldg(W + (f + 0) * FO + o);
        const float w1 = __ldg(W + (f + 1) * FO + o);
        const float w2 = __ldg(W + (f + 2) * FO + o);
        const float w3 = __ldg(W + (f + 3) * FO + o);
        #pragma unroll
        for (int q = 0; q < 4; q++) {
            const float4 y = *(const float4*)&y_s[r0 + q][f];
            accO[q] = fmaf(y.x, w0, accO[q]);
            accO[q] = fmaf(y.y, w1, accO[q]);
            accO[q] = fmaf(y.z, w2, accO[q]);
            accO[q] = fmaf(y.w, w3, accO[q]);
        }
    }

    #pragma unroll
    for (int q = 0; q < 4; q++)
        out[(size_t)(bi0 + r0 + q) * FO + o] = fmaxf(accO[q], 0.0f);
}

extern "C" void kernel_launch(void* const* d_in, const int* in_sizes, int n_in,
                              void* d_out, int out_size)
{
    const float* s1   = (const float*)d_in[0];  // (16,128,128,64)
    const float* s2   = (const float*)d_in[1];  // (16,128,128,64)
    const float* adj  = (const float*)d_in[2];  // (16,128,128)
    const float* W    = (const float*)d_in[3];  // (128,128)
    const float* bias = (const float*)d_in[4];  // (128,)
    float* out = (float*)d_out;                 // (16,128,128)

    gcn_fused2<<<(16 * 128) / RPB, 256>>>(s1, s2, adj, W, bias, out);
}